// round 7
// baseline (speedup 1.0000x reference)
#include <cuda_runtime.h>
#include <cstdint>

#define N_NODES 100000
#define N_EDGES 1600000
#define HC 128            // HEADS * OUT_CH
#define HEADS 4
#define OUT_CH 32
#define EDGE_CH 32
#define SCAN_BLK 1024
#define SCAN_NB ((N_NODES + SCAN_BLK - 1) / SCAN_BLK)   // 98
#define CSR_CAP (N_EDGES + 3 * N_NODES + 16)            // padded-to-4 segments

__constant__ float c_neg_slope = 0.2f;

// ---------------- scratch (static device globals; no allocation) ----------------
__device__ float  g_xl[(size_t)HEADS * N_NODES * OUT_CH];  // HEAD-MAJOR: [H][N][32]
__device__ float  g_al[N_NODES * HEADS];        // alpha_l per node/head ([N][4])
__device__ float  g_ar[N_NODES * HEADS];        // alpha_r per node/head
__device__ float  g_we[HC];                     // folded We^T * att_e   [H][32]
__device__ float4 g_denom[N_NODES];             // softmax denominators (sum of ex)
__device__ int    g_hist[N_NODES];              // in-degree histogram
__device__ int    g_offs[N_NODES];              // CSR start offsets (4-aligned)
__device__ int    g_cursor[N_NODES];            // scatter cursors
__device__ int    g_bsum[SCAN_NB];              // scan block totals
__device__ int    g_csr_src[CSR_CAP];           // dst-sorted source node ids
__device__ float  g_exh[(size_t)HEADS * CSR_CAP];  // HEAD-MAJOR ex planes [H][CSR_CAP]

// vectorized 16B global reduction (sm_90+)
__device__ __forceinline__ void red_add_v4(float4* p, float4 v) {
    asm volatile("red.global.add.v4.f32 [%0], {%1, %2, %3, %4};"
                 :: "l"(p), "f"(v.x), "f"(v.y), "f"(v.z), "f"(v.w)
                 : "memory");
}

// ---------------- fold We*att_e + zero hist (one kernel) ----------------
__global__ void k_fold_zero(const float* __restrict__ We, const float* __restrict__ att_e) {
    int i = blockIdx.x * blockDim.x + threadIdx.x;
    if (i < N_NODES) g_hist[i] = 0;
    if (blockIdx.x == 0 && threadIdx.x < HC) {
        int t = threadIdx.x, h = t >> 5, k = t & 31;
        float s = 0.0f;
#pragma unroll
        for (int c = 0; c < OUT_CH; c++)
            s += We[(h * OUT_CH + c) * EDGE_CH + k] * att_e[h * OUT_CH + c];
        g_we[t] = s;
    }
}

// ---------------- xl = x @ Wl^T (head-major store) + fused alpha_l/alpha_r ----------------
__global__ void k_gemm(const float* __restrict__ x, const float* __restrict__ Wl,
                       const float* __restrict__ att_l, const float* __restrict__ att_r) {
    __shared__ float xs[8][HC];
    const int j    = threadIdx.x;       // 0..127 output column (h*32 + c)
    const int lane = j & 31;            // c
    const int w    = j >> 5;            // head index
    const float al_w = att_l[j];
    const float ar_w = att_r[j];
    const float4* __restrict__ Wrow = (const float4*)(Wl + (size_t)j * HC); // 32 float4

    for (int base = blockIdx.x * 8; base < N_NODES; base += gridDim.x * 8) {
        __syncthreads();
        {
            const float4* src = (const float4*)(x + (size_t)base * HC);
            ((float4*)xs)[j]       = src[j];
            ((float4*)xs)[j + 128] = src[j + 128];
        }
        __syncthreads();

        float acc[8];
#pragma unroll
        for (int i = 0; i < 8; i++) acc[i] = 0.f;
#pragma unroll 4
        for (int k4 = 0; k4 < HC / 4; k4++) {
            float4 wv = Wrow[k4];
#pragma unroll
            for (int i = 0; i < 8; i++) {
                float4 xv = ((const float4*)xs[i])[k4];
                acc[i] += wv.x * xv.x + wv.y * xv.y + wv.z * xv.z + wv.w * xv.w;
            }
        }
#pragma unroll
        for (int i = 0; i < 8; i++) {
            // head-major: xl[h][node][c] — warp stores contiguous 128B
            g_xl[((size_t)w * N_NODES + (base + i)) * OUT_CH + lane] = acc[i];
            float pl = acc[i] * al_w;
            float pr = acc[i] * ar_w;
#pragma unroll
            for (int off = 16; off; off >>= 1) {
                pl += __shfl_xor_sync(0xffffffffu, pl, off);
                pr += __shfl_xor_sync(0xffffffffu, pr, off);
            }
            if (lane == 0) {
                g_al[(base + i) * HEADS + w] = pl;
                g_ar[(base + i) * HEADS + w] = pr;
            }
        }
    }
}

// ---------------- in-degree histogram (dst only, int4 vectorized) ----------------
__global__ void k_hist(const int* __restrict__ ei) {
    int i = blockIdx.x * blockDim.x + threadIdx.x;   // quad index
    if (i * 4 >= N_EDGES) return;
    int4 d = ((const int4*)(ei + N_EDGES))[i];
    atomicAdd(&g_hist[d.x], 1);
    atomicAdd(&g_hist[d.y], 1);
    atomicAdd(&g_hist[d.z], 1);
    atomicAdd(&g_hist[d.w], 1);
}

// ---------------- scan1: per-block exclusive scan of PADDED degrees ----------------
__global__ void k_scan1() {
    __shared__ int wsum[32];
    int i = blockIdx.x * SCAN_BLK + threadIdx.x;
    int lane = threadIdx.x & 31, wid = threadIdx.x >> 5;
    int v = (i < N_NODES) ? ((g_hist[i] + 3) & ~3) : 0;   // pad segments to mult of 4
    int inc = v;
#pragma unroll
    for (int off = 1; off < 32; off <<= 1) {
        int t = __shfl_up_sync(0xffffffffu, inc, off);
        if (lane >= off) inc += t;
    }
    if (lane == 31) wsum[wid] = inc;
    __syncthreads();
    if (wid == 0) {
        int s = wsum[lane];
#pragma unroll
        for (int off = 1; off < 32; off <<= 1) {
            int t = __shfl_up_sync(0xffffffffu, s, off);
            if (lane >= off) s += t;
        }
        wsum[lane] = s;
    }
    __syncthreads();
    int base = (wid > 0) ? wsum[wid - 1] : 0;
    if (i < N_NODES) g_offs[i] = base + inc - v;
    if (threadIdx.x == SCAN_BLK - 1) g_bsum[blockIdx.x] = base + inc;
}

// ---------------- scan23: apply block-total prefix + init cursor + zero denom ----------------
__global__ void k_scan23() {
    __shared__ int sbase;
    if (threadIdx.x < 32) {
        int acc = 0;
        for (int b = threadIdx.x; b < blockIdx.x; b += 32) acc += g_bsum[b];
#pragma unroll
        for (int off = 16; off; off >>= 1) acc += __shfl_xor_sync(0xffffffffu, acc, off);
        if (threadIdx.x == 0) sbase = acc;
    }
    __syncthreads();
    int i = blockIdx.x * SCAN_BLK + threadIdx.x;
    if (i < N_NODES) {
        int o = g_offs[i] + sbase;
        g_offs[i]   = o;
        g_cursor[i] = o;
        g_denom[i]  = make_float4(0.f, 0.f, 0.f, 0.f);
    }
}

// ---------------- fused: logits + leaky-relu + exp + denom + CSR scatter ----------------
// 8 lanes per edge: fully-coalesced edge_attr reads (4 wavefronts per LDG.128).
__global__ void k_logits(const float* __restrict__ edge_attr, const int* __restrict__ ei) {
    __shared__ float we_s[HC];
    if (threadIdx.x < HC) we_s[threadIdx.x] = g_we[threadIdx.x];
    __syncthreads();

    int t = blockIdx.x * blockDim.x + threadIdx.x;
    int e   = t >> 3;
    int sub = t & 7;
    if (e >= N_EDGES) return;

    // sub-lane 0 kicks off index loads + cursor atomic early (latency overlapped)
    int src = 0, dst = 0, pos = 0;
    if (sub == 0) {
        src = ei[e];
        dst = ei[N_EDGES + e];
        pos = atomicAdd(&g_cursor[dst], 1);
    }

    // coalesced: warp reads 4 consecutive 128B rows
    float4 v = ((const float4*)edge_attr)[e * 8 + sub];
    float4 c0 = ((const float4*)we_s)[0 * 8 + sub];
    float4 c1 = ((const float4*)we_s)[1 * 8 + sub];
    float4 c2 = ((const float4*)we_s)[2 * 8 + sub];
    float4 c3 = ((const float4*)we_s)[3 * 8 + sub];
    float p0 = v.x * c0.x + v.y * c0.y + v.z * c0.z + v.w * c0.w;
    float p1 = v.x * c1.x + v.y * c1.y + v.z * c1.z + v.w * c1.w;
    float p2 = v.x * c2.x + v.y * c2.y + v.z * c2.z + v.w * c2.w;
    float p3 = v.x * c3.x + v.y * c3.y + v.z * c3.z + v.w * c3.w;
#pragma unroll
    for (int off = 4; off; off >>= 1) {
        p0 += __shfl_down_sync(0xffffffffu, p0, off, 8);
        p1 += __shfl_down_sync(0xffffffffu, p1, off, 8);
        p2 += __shfl_down_sync(0xffffffffu, p2, off, 8);
        p3 += __shfl_down_sync(0xffffffffu, p3, off, 8);
    }
    if (sub == 0) {
        float4 al = ((const float4*)g_al)[src];
        float4 ar = ((const float4*)g_ar)[dst];
        float a0 = al.x + ar.x + p0;
        float a1 = al.y + ar.y + p1;
        float a2 = al.z + ar.z + p2;
        float a3 = al.w + ar.w + p3;
        a0 = (a0 > 0.f) ? a0 : c_neg_slope * a0;
        a1 = (a1 > 0.f) ? a1 : c_neg_slope * a1;
        a2 = (a2 > 0.f) ? a2 : c_neg_slope * a2;
        a3 = (a3 > 0.f) ? a3 : c_neg_slope * a3;
        float4 ex = make_float4(__expf(a0), __expf(a1), __expf(a2), __expf(a3));
        g_csr_src[pos] = src;
        g_exh[pos]                       = ex.x;   // head-major planes
        g_exh[(size_t)CSR_CAP + pos]     = ex.y;
        g_exh[(size_t)2 * CSR_CAP + pos] = ex.z;
        g_exh[(size_t)3 * CSR_CAP + pos] = ex.w;
        red_add_v4(&g_denom[dst], ex);
    }
}

// ---------------- gather aggregation: warp per (head, node), head-outermost passes ----------------
// per pass the 12.8MB xl head-plane is L2-resident; per-edge gather = one 128B line.
__global__ void k_agg(const float* __restrict__ bias, float* __restrict__ out) {
    int wg = blockIdx.x * (blockDim.x >> 5) + (threadIdx.x >> 5);
    if (wg >= HEADS * N_NODES) return;
    int h    = wg / N_NODES;            // head outermost -> temporal head passes
    int node = wg - h * N_NODES;
    const int c = threadIdx.x & 31;

    int beg = g_offs[node];             // 4-aligned
    int end = g_cursor[node];           // beg + degree
    const float* __restrict__ exp_h = g_exh + (size_t)h * CSR_CAP;
    const float* __restrict__ xlh   = g_xl + (size_t)h * N_NODES * OUT_CH;

    float acc = 0.f;
    int pos = beg;
    for (; pos + 3 < end; pos += 4) {
        int4   s = *(const int4*)(g_csr_src + pos);      // uniform broadcast
        float4 a = *(const float4*)(exp_h + pos);        // uniform broadcast (4-aligned)
        float v0 = xlh[(size_t)s.x * OUT_CH + c];        // 128B line per edge
        float v1 = xlh[(size_t)s.y * OUT_CH + c];
        float v2 = xlh[(size_t)s.z * OUT_CH + c];
        float v3 = xlh[(size_t)s.w * OUT_CH + c];
        acc += a.x * v0 + a.y * v1 + a.z * v2 + a.w * v3;
    }
    for (; pos < end; pos++) {
        int s = g_csr_src[pos];
        acc += exp_h[pos] * xlh[(size_t)s * OUT_CH + c];
    }
    float den = ((const float*)g_denom)[(size_t)node * 4 + h];
    float o = acc / (den + 1e-16f) + bias[h * OUT_CH + c];
    out[(size_t)node * HC + h * OUT_CH + c] = o;       // 128B coalesced store
}

// ---------------- launch ----------------
extern "C" void kernel_launch(void* const* d_in, const int* in_sizes, int n_in,
                              void* d_out, int out_size) {
    const float* x         = (const float*)d_in[0];
    const float* edge_attr = (const float*)d_in[1];
    const float* Wl        = (const float*)d_in[2];
    const float* We        = (const float*)d_in[3];
    const float* att_l     = (const float*)d_in[4];
    const float* att_r     = (const float*)d_in[5];
    const float* att_e     = (const float*)d_in[6];
    const float* bias      = (const float*)d_in[7];
    const int*   ei        = (const int*)d_in[8];
    float* out = (float*)d_out;

    k_fold_zero<<<SCAN_NB, SCAN_BLK>>>(We, att_e);                  // launch 0
    k_gemm<<<2368, 128>>>(x, Wl, att_l, att_r);                     // launch 1
    k_hist<<<(N_EDGES / 4 + 255) / 256, 256>>>(ei);                 // launch 2
    k_scan1<<<SCAN_NB, SCAN_BLK>>>();                               // launch 3
    k_scan23<<<SCAN_NB, SCAN_BLK>>>();                              // launch 4
    k_logits<<<(N_EDGES * 8 + 255) / 256, 256>>>(edge_attr, ei);    // launch 5 (profiled)
    k_agg<<<(HEADS * N_NODES * 32 + 255) / 256, 256>>>(bias, out);  // launch 6
}

// round 8
// speedup vs baseline: 1.0588x; 1.0588x over previous
#include <cuda_runtime.h>
#include <cstdint>

#define N_NODES 100000
#define N_EDGES 1600000
#define HC 128            // HEADS * OUT_CH
#define HEADS 4
#define OUT_CH 32
#define EDGE_CH 32
#define SCAN_BLK 1024
#define SCAN_NB ((N_NODES + SCAN_BLK - 1) / SCAN_BLK)   // 98
#define LOG_BLK 256       // edges per logits block (1600000 % 256 == 0... actually 6250 blocks exactly)

__constant__ float c_neg_slope = 0.2f;

// ---------------- scratch (static device globals; no allocation) ----------------
__device__ float  g_xl[(size_t)N_NODES * HC];   // 51.2 MB projected node features [N][128]
__device__ float  g_al[N_NODES * HEADS];        // alpha_l per node/head
__device__ float  g_ar[N_NODES * HEADS];        // alpha_r per node/head
__device__ float  g_we[HC];                     // folded We^T * att_e  [H][32]
__device__ float4 g_denom[N_NODES];             // softmax denominators (sum of ex)
__device__ int    g_hist[N_NODES];              // in-degree histogram
__device__ int    g_offs[N_NODES];              // CSR start offsets (exclusive scan)
__device__ int    g_cursor[N_NODES];            // scatter cursors
__device__ int    g_bsum[SCAN_NB];              // scan block sums
__device__ int    g_csr_src[N_EDGES];           // dst-sorted source node ids
__device__ float4 g_csr_ex[N_EDGES];            // dst-sorted UNnormalized exp(logit)

// vectorized 16B global reduction (sm_90+)
__device__ __forceinline__ void red_add_v4(float4* p, float4 v) {
    asm volatile("red.global.add.v4.f32 [%0], {%1, %2, %3, %4};"
                 :: "l"(p), "f"(v.x), "f"(v.y), "f"(v.z), "f"(v.w)
                 : "memory");
}

// ---------------- zero hist + denom ----------------
__global__ void k_zero() {
    int idx = blockIdx.x * blockDim.x + threadIdx.x;
    if (idx < N_NODES * HEADS) ((float*)g_denom)[idx] = 0.0f;
    if (idx < N_NODES) g_hist[idx] = 0;
}

// ---------------- fold We with att_e  ->  g_we[h*32+k] ----------------
__global__ void k_wepre(const float* __restrict__ We, const float* __restrict__ att_e) {
    int t = threadIdx.x;           // 0..127  = h*32 + k
    int h = t >> 5, k = t & 31;
    float s = 0.0f;
#pragma unroll
    for (int c = 0; c < OUT_CH; c++)
        s += We[(h * OUT_CH + c) * EDGE_CH + k] * att_e[h * OUT_CH + c];
    g_we[t] = s;
}

// ---------------- in-degree histogram (dst only, int4 vectorized) ----------------
__global__ void k_hist(const int* __restrict__ ei) {
    int i = blockIdx.x * blockDim.x + threadIdx.x;   // quad index
    if (i * 4 >= N_EDGES) return;
    int4 d = ((const int4*)(ei + N_EDGES))[i];
    atomicAdd(&g_hist[d.x], 1);
    atomicAdd(&g_hist[d.y], 1);
    atomicAdd(&g_hist[d.z], 1);
    atomicAdd(&g_hist[d.w], 1);
}

// ---------------- xl = x @ Wl^T, plus alpha_l / alpha_r (8-node tiles) ----------------
__global__ void k_gemm(const float* __restrict__ x, const float* __restrict__ Wl,
                       const float* __restrict__ att_l, const float* __restrict__ att_r) {
    __shared__ float xs[8][HC];
    const int j    = threadIdx.x;       // 0..127 output column
    const int lane = j & 31;
    const int w    = j >> 5;            // head index
    const float al_w = att_l[j];
    const float ar_w = att_r[j];
    const float4* __restrict__ Wrow = (const float4*)(Wl + (size_t)j * HC); // 32 float4

    for (int base = blockIdx.x * 8; base < N_NODES; base += gridDim.x * 8) {
        __syncthreads();
        {
            const float4* src = (const float4*)(x + (size_t)base * HC);
            ((float4*)xs)[j]       = src[j];
            ((float4*)xs)[j + 128] = src[j + 128];
        }
        __syncthreads();

        float acc[8];
#pragma unroll
        for (int i = 0; i < 8; i++) acc[i] = 0.f;
#pragma unroll 4
        for (int k4 = 0; k4 < HC / 4; k4++) {
            float4 wv = Wrow[k4];
#pragma unroll
            for (int i = 0; i < 8; i++) {
                float4 xv = ((const float4*)xs[i])[k4];
                acc[i] += wv.x * xv.x + wv.y * xv.y + wv.z * xv.z + wv.w * xv.w;
            }
        }
#pragma unroll
        for (int i = 0; i < 8; i++) {
            g_xl[(size_t)(base + i) * HC + j] = acc[i];
            float pl = acc[i] * al_w;
            float pr = acc[i] * ar_w;
#pragma unroll
            for (int off = 16; off; off >>= 1) {
                pl += __shfl_xor_sync(0xffffffffu, pl, off);
                pr += __shfl_xor_sync(0xffffffffu, pr, off);
            }
            if (lane == 0) {
                g_al[(base + i) * HEADS + w] = pl;
                g_ar[(base + i) * HEADS + w] = pr;
            }
        }
    }
}

// ---------------- scan kernels: exclusive prefix over g_hist -> g_offs ----------------
__global__ void k_scan1() {
    __shared__ int wsum[32];
    int i = blockIdx.x * SCAN_BLK + threadIdx.x;
    int lane = threadIdx.x & 31, wid = threadIdx.x >> 5;
    int v = (i < N_NODES) ? g_hist[i] : 0;
    int inc = v;
#pragma unroll
    for (int off = 1; off < 32; off <<= 1) {
        int t = __shfl_up_sync(0xffffffffu, inc, off);
        if (lane >= off) inc += t;
    }
    if (lane == 31) wsum[wid] = inc;
    __syncthreads();
    if (wid == 0) {
        int s = wsum[lane];
#pragma unroll
        for (int off = 1; off < 32; off <<= 1) {
            int t = __shfl_up_sync(0xffffffffu, s, off);
            if (lane >= off) s += t;
        }
        wsum[lane] = s;
    }
    __syncthreads();
    int base = (wid > 0) ? wsum[wid - 1] : 0;
    if (i < N_NODES) g_offs[i] = base + inc - v;
    if (threadIdx.x == SCAN_BLK - 1) g_bsum[blockIdx.x] = base + inc;
}

__global__ void k_scan2() {   // single block, scan SCAN_NB (=98) block totals, exclusive
    __shared__ int wsum[4];
    int lane = threadIdx.x & 31, wid = threadIdx.x >> 5;
    int v = (threadIdx.x < SCAN_NB) ? g_bsum[threadIdx.x] : 0;
    int inc = v;
#pragma unroll
    for (int off = 1; off < 32; off <<= 1) {
        int t = __shfl_up_sync(0xffffffffu, inc, off);
        if (lane >= off) inc += t;
    }
    if (lane == 31) wsum[wid] = inc;
    __syncthreads();
    int base = 0;
    for (int w = 0; w < wid; w++) base += wsum[w];
    if (threadIdx.x < SCAN_NB) g_bsum[threadIdx.x] = base + inc - v;
}

__global__ void k_scan3() {   // apply block offsets; init cursor = offs
    int i = blockIdx.x * SCAN_BLK + threadIdx.x;
    if (i < N_NODES) {
        int o = g_offs[i] + g_bsum[blockIdx.x];
        g_offs[i]   = o;
        g_cursor[i] = o;
    }
}

// ---------------- fused: logits + leaky-relu + exp + denom + CSR scatter ----------------
// smem-staged: block cooperatively loads 256 edge rows coalesced (1 wf/edge instead of 8),
// then thread-per-edge computes from conflict-free stride-33 smem tile.
__global__ void k_logits(const float* __restrict__ edge_attr, const int* __restrict__ ei) {
    __shared__ float we_s[HC];
    __shared__ float tile[LOG_BLK][33];      // stride 33 floats -> conflict-free rows
    const int t = threadIdx.x;
    if (t < HC) we_s[t] = g_we[t];

    const int base = blockIdx.x * LOG_BLK;   // N_EDGES % LOG_BLK == 0 (6250 blocks)
    {   // cooperative coalesced load: 2048 float4 per block
        const float4* __restrict__ src4 = (const float4*)(edge_attr + (size_t)base * EDGE_CH);
#pragma unroll
        for (int i = 0; i < 8; i++) {
            int g = t + i * LOG_BLK;
            float4 v = src4[g];
            int r = g >> 3, q = (g & 7) * 4;
            tile[r][q + 0] = v.x; tile[r][q + 1] = v.y;
            tile[r][q + 2] = v.z; tile[r][q + 3] = v.w;
        }
    }
    // per-edge index loads + cursor slot early: ~320cyc ATOMG latency hidden by staging/sync
    const int e   = base + t;
    const int src = ei[e];
    const int dst = ei[N_EDGES + e];
    int pos = atomicAdd(&g_cursor[dst], 1);
    __syncthreads();

    const float* __restrict__ row = tile[t];
    float p0 = 0.f, p1 = 0.f, p2 = 0.f, p3 = 0.f;
#pragma unroll
    for (int k = 0; k < EDGE_CH; k++) {
        float v = row[k];                    // conflict-free: bank (t+k) mod 32
        p0 += v * we_s[k];
        p1 += v * we_s[32 + k];
        p2 += v * we_s[64 + k];
        p3 += v * we_s[96 + k];
    }
    float4 al = ((const float4*)g_al)[src];
    float4 ar = ((const float4*)g_ar)[dst];
    float a0 = al.x + ar.x + p0;
    float a1 = al.y + ar.y + p1;
    float a2 = al.z + ar.z + p2;
    float a3 = al.w + ar.w + p3;
    a0 = (a0 > 0.f) ? a0 : c_neg_slope * a0;
    a1 = (a1 > 0.f) ? a1 : c_neg_slope * a1;
    a2 = (a2 > 0.f) ? a2 : c_neg_slope * a2;
    a3 = (a3 > 0.f) ? a3 : c_neg_slope * a3;
    float4 ex = make_float4(__expf(a0), __expf(a1), __expf(a2), __expf(a3));
    g_csr_src[pos] = src;
    g_csr_ex[pos]  = ex;
    red_add_v4(&g_denom[dst], ex);
}

// ---------------- gather aggregation: warp per (channel-half, node) ----------------
// halves run temporally (half index outermost): per-pass xl footprint = 25.6MB of
// 128B-aligned half-lines + ex + out-half fits L2 -> gathers hit L2, not DRAM.
__global__ void k_agg(const float* __restrict__ bias, float* __restrict__ out) {
    int wg = blockIdx.x * (blockDim.x >> 5) + (threadIdx.x >> 5);
    if (wg >= 2 * N_NODES) return;
    const int half = wg / N_NODES;             // 0 or 1, outermost in schedule
    const int node = wg - half * N_NODES;
    const int lane = threadIdx.x & 31;
    const int c2   = half * 32 + lane;         // float2 index within 64-float2 row
    const int h    = c2 >> 4;                  // head for this channel pair

    int beg = g_offs[node];
    int end = g_cursor[node];                  // beg + degree
    const float*  __restrict__ exs = (const float*)g_csr_ex;
    const float2* __restrict__ xl2 = (const float2*)g_xl;
    float2 acc = make_float2(0.f, 0.f);

    int pos = beg;
    for (; pos + 3 < end; pos += 4) {
        int s0 = g_csr_src[pos];
        int s1 = g_csr_src[pos + 1];
        int s2 = g_csr_src[pos + 2];
        int s3 = g_csr_src[pos + 3];
        float a0 = exs[(size_t)(pos + 0) * 4 + h];
        float a1 = exs[(size_t)(pos + 1) * 4 + h];
        float a2 = exs[(size_t)(pos + 2) * 4 + h];
        float a3 = exs[(size_t)(pos + 3) * 4 + h];
        float2 v0 = xl2[(size_t)s0 * 64 + c2];   // 256B line-pair per edge, L2-hot
        float2 v1 = xl2[(size_t)s1 * 64 + c2];
        float2 v2 = xl2[(size_t)s2 * 64 + c2];
        float2 v3 = xl2[(size_t)s3 * 64 + c2];
        acc.x += a0 * v0.x + a1 * v1.x + a2 * v2.x + a3 * v3.x;
        acc.y += a0 * v0.y + a1 * v1.y + a2 * v2.y + a3 * v3.y;
    }
    for (; pos < end; pos++) {
        int s0 = g_csr_src[pos];
        float a0 = exs[(size_t)pos * 4 + h];
        float2 v0 = xl2[(size_t)s0 * 64 + c2];
        acc.x += a0 * v0.x;
        acc.y += a0 * v0.y;
    }
    float inv = 1.0f / (((const float*)g_denom)[(size_t)node * 4 + h] + 1e-16f);
    float2 b = ((const float2*)bias)[c2];
    acc.x = acc.x * inv + b.x;
    acc.y = acc.y * inv + b.y;
    ((float2*)out)[(size_t)node * 64 + c2] = acc;   // coalesced 256B half-row store
}

// ---------------- launch ----------------
extern "C" void kernel_launch(void* const* d_in, const int* in_sizes, int n_in,
                              void* d_out, int out_size) {
    const float* x         = (const float*)d_in[0];
    const float* edge_attr = (const float*)d_in[1];
    const float* Wl        = (const float*)d_in[2];
    const float* We        = (const float*)d_in[3];
    const float* att_l     = (const float*)d_in[4];
    const float* att_r     = (const float*)d_in[5];
    const float* att_e     = (const float*)d_in[6];
    const float* bias      = (const float*)d_in[7];
    const int*   ei        = (const int*)d_in[8];
    float* out = (float*)d_out;

    k_zero<<<(N_NODES * HEADS + 255) / 256, 256>>>();
    k_wepre<<<1, 128>>>(We, att_e);
    k_hist<<<(N_EDGES / 4 + 255) / 256, 256>>>(ei);
    k_scan1<<<SCAN_NB, SCAN_BLK>>>();
    k_scan2<<<1, 128>>>();
    k_scan3<<<SCAN_NB, SCAN_BLK>>>();
    k_gemm<<<2368, 128>>>(x, Wl, att_l, att_r);
    k_logits<<<N_EDGES / LOG_BLK, LOG_BLK>>>(edge_attr, ei);
    k_agg<<<(2 * N_NODES * 32 + 255) / 256, 256>>>(bias, out);
}

// round 9
// speedup vs baseline: 1.2531x; 1.1835x over previous
#include <cuda_runtime.h>
#include <cstdint>

#define N_NODES 100000
#define N_EDGES 1600000
#define HC 128            // HEADS * OUT_CH
#define HEADS 4
#define OUT_CH 32
#define EDGE_CH 32
#define SCAN_BLK 1024
#define SCAN_NB ((N_NODES + SCAN_BLK - 1) / SCAN_BLK)   // 98

__constant__ float c_neg_slope = 0.2f;

// ---------------- scratch (static device globals; no allocation) ----------------
__device__ float  g_xl[(size_t)N_NODES * HC];   // 51.2 MB projected node features
__device__ float  g_al[N_NODES * HEADS];        // alpha_l per node/head
__device__ float  g_ar[N_NODES * HEADS];        // alpha_r per node/head
__device__ float  g_we[HC];                     // folded We^T * att_e  [H][32]
__device__ float4 g_denom[N_NODES];             // softmax denominators (sum of ex)
__device__ int    g_hist[N_NODES];              // in-degree histogram
__device__ int    g_offs[N_NODES];              // CSR start offsets (exclusive scan)
__device__ int    g_cursor[N_NODES];            // scatter cursors
__device__ int    g_bsum[SCAN_NB];              // scan block sums
__device__ int    g_csr_src[N_EDGES];           // dst-sorted source node ids
__device__ float4 g_csr_ex[N_EDGES];            // dst-sorted UNnormalized exp(logit)

// vectorized 16B global reduction (sm_90+)
__device__ __forceinline__ void red_add_v4(float4* p, float4 v) {
    asm volatile("red.global.add.v4.f32 [%0], {%1, %2, %3, %4};"
                 :: "l"(p), "f"(v.x), "f"(v.y), "f"(v.z), "f"(v.w)
                 : "memory");
}

// ---------------- zero hist + denom ----------------
__global__ void k_zero() {
    int idx = blockIdx.x * blockDim.x + threadIdx.x;
    if (idx < N_NODES * HEADS) ((float*)g_denom)[idx] = 0.0f;
    if (idx < N_NODES) g_hist[idx] = 0;
}

// ---------------- fold We with att_e  ->  g_we[h*32+k] ----------------
__global__ void k_wepre(const float* __restrict__ We, const float* __restrict__ att_e) {
    int t = threadIdx.x;           // 0..127  = h*32 + k
    int h = t >> 5, k = t & 31;
    float s = 0.0f;
#pragma unroll
    for (int c = 0; c < OUT_CH; c++)
        s += We[(h * OUT_CH + c) * EDGE_CH + k] * att_e[h * OUT_CH + c];
    g_we[t] = s;
}

// ---------------- in-degree histogram (dst only, int4 vectorized) ----------------
__global__ void k_hist(const int* __restrict__ ei) {
    int i = blockIdx.x * blockDim.x + threadIdx.x;   // quad index
    if (i * 4 >= N_EDGES) return;
    int4 d = ((const int4*)(ei + N_EDGES))[i];
    atomicAdd(&g_hist[d.x], 1);
    atomicAdd(&g_hist[d.y], 1);
    atomicAdd(&g_hist[d.z], 1);
    atomicAdd(&g_hist[d.w], 1);
}

// ---------------- xl = x @ Wl^T, plus alpha_l / alpha_r (8-node tiles) ----------------
__global__ void k_gemm(const float* __restrict__ x, const float* __restrict__ Wl,
                       const float* __restrict__ att_l, const float* __restrict__ att_r) {
    __shared__ float xs[8][HC];
    const int j    = threadIdx.x;       // 0..127 output column
    const int lane = j & 31;
    const int w    = j >> 5;            // head index
    const float al_w = att_l[j];
    const float ar_w = att_r[j];
    const float4* __restrict__ Wrow = (const float4*)(Wl + (size_t)j * HC); // 32 float4

    for (int base = blockIdx.x * 8; base < N_NODES; base += gridDim.x * 8) {
        __syncthreads();
        {
            const float4* src = (const float4*)(x + (size_t)base * HC);
            ((float4*)xs)[j]       = src[j];
            ((float4*)xs)[j + 128] = src[j + 128];
        }
        __syncthreads();

        float acc[8];
#pragma unroll
        for (int i = 0; i < 8; i++) acc[i] = 0.f;
#pragma unroll 4
        for (int k4 = 0; k4 < HC / 4; k4++) {
            float4 wv = Wrow[k4];
#pragma unroll
            for (int i = 0; i < 8; i++) {
                float4 xv = ((const float4*)xs[i])[k4];
                acc[i] += wv.x * xv.x + wv.y * xv.y + wv.z * xv.z + wv.w * xv.w;
            }
        }
#pragma unroll
        for (int i = 0; i < 8; i++) {
            g_xl[(size_t)(base + i) * HC + j] = acc[i];
            float pl = acc[i] * al_w;
            float pr = acc[i] * ar_w;
#pragma unroll
            for (int off = 16; off; off >>= 1) {
                pl += __shfl_xor_sync(0xffffffffu, pl, off);
                pr += __shfl_xor_sync(0xffffffffu, pr, off);
            }
            if (lane == 0) {
                g_al[(base + i) * HEADS + w] = pl;
                g_ar[(base + i) * HEADS + w] = pr;
            }
        }
    }
}

// ---------------- scan kernels: exclusive prefix over g_hist -> g_offs ----------------
__global__ void k_scan1() {
    __shared__ int wsum[32];
    int i = blockIdx.x * SCAN_BLK + threadIdx.x;
    int lane = threadIdx.x & 31, wid = threadIdx.x >> 5;
    int v = (i < N_NODES) ? g_hist[i] : 0;
    int inc = v;
#pragma unroll
    for (int off = 1; off < 32; off <<= 1) {
        int t = __shfl_up_sync(0xffffffffu, inc, off);
        if (lane >= off) inc += t;
    }
    if (lane == 31) wsum[wid] = inc;
    __syncthreads();
    if (wid == 0) {
        int s = wsum[lane];
#pragma unroll
        for (int off = 1; off < 32; off <<= 1) {
            int t = __shfl_up_sync(0xffffffffu, s, off);
            if (lane >= off) s += t;
        }
        wsum[lane] = s;
    }
    __syncthreads();
    int base = (wid > 0) ? wsum[wid - 1] : 0;
    if (i < N_NODES) g_offs[i] = base + inc - v;
    if (threadIdx.x == SCAN_BLK - 1) g_bsum[blockIdx.x] = base + inc;
}

__global__ void k_scan2() {   // single block, scan SCAN_NB (=98) block totals, exclusive
    __shared__ int wsum[4];
    int lane = threadIdx.x & 31, wid = threadIdx.x >> 5;
    int v = (threadIdx.x < SCAN_NB) ? g_bsum[threadIdx.x] : 0;
    int inc = v;
#pragma unroll
    for (int off = 1; off < 32; off <<= 1) {
        int t = __shfl_up_sync(0xffffffffu, inc, off);
        if (lane >= off) inc += t;
    }
    if (lane == 31) wsum[wid] = inc;
    __syncthreads();
    int base = 0;
    for (int w = 0; w < wid; w++) base += wsum[w];
    if (threadIdx.x < SCAN_NB) g_bsum[threadIdx.x] = base + inc - v;
}

__global__ void k_scan3() {   // apply block offsets; init cursor = offs
    int i = blockIdx.x * SCAN_BLK + threadIdx.x;
    if (i < N_NODES) {
        int o = g_offs[i] + g_bsum[blockIdx.x];
        g_offs[i]   = o;
        g_cursor[i] = o;
    }
}

// ---------------- fused: logits + leaky-relu + exp + denom + CSR scatter ----------------
// thread per edge; shift-free softmax; scatter UNnormalized ex into CSR slot.
__global__ void k_logits(const float* __restrict__ edge_attr, const int* __restrict__ ei) {
    __shared__ float we_s[HC];
    if (threadIdx.x < HC) we_s[threadIdx.x] = g_we[threadIdx.x];
    __syncthreads();

    int e = blockIdx.x * blockDim.x + threadIdx.x;
    if (e >= N_EDGES) return;

    const float4* __restrict__ row = (const float4*)(edge_attr + (size_t)e * EDGE_CH);
    const float4* w0 = (const float4*)(we_s);
    const float4* w1 = (const float4*)(we_s + 32);
    const float4* w2 = (const float4*)(we_s + 64);
    const float4* w3 = (const float4*)(we_s + 96);
    float p0 = 0.f, p1 = 0.f, p2 = 0.f, p3 = 0.f;
#pragma unroll
    for (int i = 0; i < 8; i++) {
        float4 v = row[i];
        float4 a0 = w0[i], a1 = w1[i], a2 = w2[i], a3 = w3[i];
        p0 += v.x * a0.x + v.y * a0.y + v.z * a0.z + v.w * a0.w;
        p1 += v.x * a1.x + v.y * a1.y + v.z * a1.z + v.w * a1.w;
        p2 += v.x * a2.x + v.y * a2.y + v.z * a2.z + v.w * a2.w;
        p3 += v.x * a3.x + v.y * a3.y + v.z * a3.z + v.w * a3.w;
    }
    int src = ei[e];
    int dst = ei[N_EDGES + e];
    float4 al = ((const float4*)g_al)[src];
    float4 ar = ((const float4*)g_ar)[dst];
    float a0 = al.x + ar.x + p0;
    float a1 = al.y + ar.y + p1;
    float a2 = al.z + ar.z + p2;
    float a3 = al.w + ar.w + p3;
    a0 = (a0 > 0.f) ? a0 : c_neg_slope * a0;
    a1 = (a1 > 0.f) ? a1 : c_neg_slope * a1;
    a2 = (a2 > 0.f) ? a2 : c_neg_slope * a2;
    a3 = (a3 > 0.f) ? a3 : c_neg_slope * a3;
    float4 ex = make_float4(__expf(a0), __expf(a1), __expf(a2), __expf(a3));
    int pos = atomicAdd(&g_cursor[dst], 1);
    g_csr_src[pos] = src;
    g_csr_ex[pos]  = ex;
    red_add_v4(&g_denom[dst], ex);
}

// ---------------- gather aggregation: one warp per dst node ----------------
// normalize by denom in the epilogue:  out = (sum ex_i * xl[src_i]) / (denom+eps) + bias
__global__ void k_agg(const float* __restrict__ bias, float* __restrict__ out) {
    const int lane = threadIdx.x & 31;
    const int h    = lane >> 3;                 // head owning this lane's float4
    int node = blockIdx.x * (blockDim.x >> 5) + (threadIdx.x >> 5);
    if (node >= N_NODES) return;

    int beg = g_offs[node];
    int end = g_cursor[node];                   // start + degree
    float4 acc = make_float4(0.f, 0.f, 0.f, 0.f);

    int pos = beg;
    for (; pos + 3 < end; pos += 4) {
        int s0 = g_csr_src[pos];
        int s1 = g_csr_src[pos + 1];
        int s2 = g_csr_src[pos + 2];
        int s3 = g_csr_src[pos + 3];
        float a0 = ((const float*)g_csr_ex)[(size_t)pos * 4 + h];
        float a1 = ((const float*)g_csr_ex)[(size_t)(pos + 1) * 4 + h];
        float a2 = ((const float*)g_csr_ex)[(size_t)(pos + 2) * 4 + h];
        float a3 = ((const float*)g_csr_ex)[(size_t)(pos + 3) * 4 + h];
        float4 v0 = ((const float4*)g_xl)[(size_t)s0 * 32 + lane];
        float4 v1 = ((const float4*)g_xl)[(size_t)s1 * 32 + lane];
        float4 v2 = ((const float4*)g_xl)[(size_t)s2 * 32 + lane];
        float4 v3 = ((const float4*)g_xl)[(size_t)s3 * 32 + lane];
        acc.x += a0 * v0.x + a1 * v1.x + a2 * v2.x + a3 * v3.x;
        acc.y += a0 * v0.y + a1 * v1.y + a2 * v2.y + a3 * v3.y;
        acc.z += a0 * v0.z + a1 * v1.z + a2 * v2.z + a3 * v3.z;
        acc.w += a0 * v0.w + a1 * v1.w + a2 * v2.w + a3 * v3.w;
    }
    for (; pos < end; pos++) {
        int s0 = g_csr_src[pos];
        float a0 = ((const float*)g_csr_ex)[(size_t)pos * 4 + h];
        float4 v0 = ((const float4*)g_xl)[(size_t)s0 * 32 + lane];
        acc.x += a0 * v0.x; acc.y += a0 * v0.y; acc.z += a0 * v0.z; acc.w += a0 * v0.w;
    }
    float inv = 1.0f / (((const float*)g_denom)[(size_t)node * 4 + h] + 1e-16f);
    float4 b = ((const float4*)bias)[lane];
    acc.x = acc.x * inv + b.x;
    acc.y = acc.y * inv + b.y;
    acc.z = acc.z * inv + b.z;
    acc.w = acc.w * inv + b.w;
    ((float4*)out)[(size_t)node * 32 + lane] = acc;
}

// ---------------- launch: R4 kernels, forked schedule (gemm || edge-prep chain) ----------------
extern "C" void kernel_launch(void* const* d_in, const int* in_sizes, int n_in,
                              void* d_out, int out_size) {
    const float* x         = (const float*)d_in[0];
    const float* edge_attr = (const float*)d_in[1];
    const float* Wl        = (const float*)d_in[2];
    const float* We        = (const float*)d_in[3];
    const float* att_l     = (const float*)d_in[4];
    const float* att_r     = (const float*)d_in[5];
    const float* att_e     = (const float*)d_in[6];
    const float* bias      = (const float*)d_in[7];
    const int*   ei        = (const int*)d_in[8];
    float* out = (float*)d_out;

    // fork two side branches off the captured (default) stream, join before k_logits.
    cudaStream_t sA, sB;
    cudaStreamCreateWithFlags(&sA, cudaStreamNonBlocking);
    cudaStreamCreateWithFlags(&sB, cudaStreamNonBlocking);
    cudaEvent_t evRoot, evA, evB;
    cudaEventCreateWithFlags(&evRoot, cudaEventDisableTiming);
    cudaEventCreateWithFlags(&evA,    cudaEventDisableTiming);
    cudaEventCreateWithFlags(&evB,    cudaEventDisableTiming);

    cudaEventRecord(evRoot, 0);
    cudaStreamWaitEvent(sA, evRoot, 0);
    cudaStreamWaitEvent(sB, evRoot, 0);

    // Branch A (sA): edge-prep chain — zero, hist, scans
    k_zero <<<(N_NODES * HEADS + 255) / 256, 256, 0, sA>>>();
    k_hist <<<(N_EDGES / 4 + 255) / 256, 256, 0, sA>>>(ei);
    k_scan1<<<SCAN_NB, SCAN_BLK, 0, sA>>>();
    k_scan2<<<1, 128, 0, sA>>>();
    k_scan3<<<SCAN_NB, SCAN_BLK, 0, sA>>>();
    cudaEventRecord(evA, sA);

    // Branch B (sB): tiny weight fold
    k_wepre<<<1, 128, 0, sB>>>(We, att_e);
    cudaEventRecord(evB, sB);

    // Main stream: FMA-bound GEMM overlaps branch A's L2/atomic work
    k_gemm<<<2368, 128>>>(x, Wl, att_l, att_r);

    // join
    cudaStreamWaitEvent(0, evA, 0);
    cudaStreamWaitEvent(0, evB, 0);

    k_logits<<<(N_EDGES + 255) / 256, 256>>>(edge_attr, ei);
    k_agg<<<(N_NODES * 32 + 255) / 256, 256>>>(bias, out);

    cudaEventDestroy(evRoot);
    cudaEventDestroy(evA);
    cudaEventDestroy(evB);
    cudaStreamDestroy(sA);
    cudaStreamDestroy(sB);
}